// round 2
// baseline (speedup 1.0000x reference)
#include <cuda_runtime.h>
#include <cstdint>

// Problem constants
#define NB   64
#define LQg  1024
#define LKg  1024
#define DH   64
#define TQ   32          // queries per CTA
#define KT   128         // key tile
#define KTP  132         // padded stride for K tile in smem (bank-conflict relief, float4-aligned)
#define NT   256         // threads per CTA

#define SMEM_FLOATS (TQ*LKg + DH*TQ + DH*KTP)   // scores + qT + kv buffer
#define NEG_BIG (-1.0e30f)

__global__ __launch_bounds__(NT, 1)
void sparse_attn_kernel(const float* __restrict__ Q, const float* __restrict__ K,
                        const float* __restrict__ V, const int* __restrict__ M,
                        float* __restrict__ Out, float* __restrict__ Attn)
{
    extern __shared__ float sm[];
    float* s_sc = sm;                       // [TQ][LKg]      = 32768 floats
    float* s_q  = s_sc + TQ * LKg;          // [DH][TQ]       = 2048 floats (transposed, pre-scaled)
    float* s_kv = s_q + DH * TQ;            // K: [DH][KTP] (8448) / V: [KT][DH] (8192)

    const int t  = threadIdx.x;
    const int b  = blockIdx.x >> 5;                 // LQg/TQ = 32 tiles per batch
    const int q0 = (blockIdx.x & 31) * TQ;

    // ---- load Q tile (scaled by 1/TEMPERATURE, transposed to [d][q]) ----
    const float* qg = Q + ((size_t)b * LQg + q0) * DH;
    for (int e = t; e < TQ * DH; e += NT) {
        int qi = e >> 6, d = e & 63;
        s_q[d * TQ + qi] = qg[e] * 0.125f;
    }

    const int qi0 = (t >> 5) << 2;   // 4 query rows per thread
    const int ki0 = (t & 31) << 2;   // 4 key cols per thread

    // ================= Phase 1: S = (Q/T) @ K^T =================
    const float* kg = K + (size_t)b * LKg * DH;
    for (int kt = 0; kt < LKg; kt += KT) {
        __syncthreads();  // protect s_kv reuse / s_q first pass
        for (int e = t; e < KT * DH; e += NT) {
            int kj = e >> 6, d = e & 63;
            s_kv[d * KTP + kj] = kg[(size_t)(kt + kj) * DH + d];
        }
        __syncthreads();

        float acc[4][4];
        #pragma unroll
        for (int r = 0; r < 4; r++)
            #pragma unroll
            for (int c = 0; c < 4; c++) acc[r][c] = 0.0f;

        #pragma unroll 16
        for (int d = 0; d < DH; d++) {
            float4 a  = *(const float4*)(s_q  + d * TQ  + qi0);   // broadcast within warp
            float4 bb = *(const float4*)(s_kv + d * KTP + ki0);   // conflict-free
            acc[0][0] += a.x * bb.x; acc[0][1] += a.x * bb.y; acc[0][2] += a.x * bb.z; acc[0][3] += a.x * bb.w;
            acc[1][0] += a.y * bb.x; acc[1][1] += a.y * bb.y; acc[1][2] += a.y * bb.z; acc[1][3] += a.y * bb.w;
            acc[2][0] += a.z * bb.x; acc[2][1] += a.z * bb.y; acc[2][2] += a.z * bb.z; acc[2][3] += a.z * bb.w;
            acc[3][0] += a.w * bb.x; acc[3][1] += a.w * bb.y; acc[3][2] += a.w * bb.z; acc[3][3] += a.w * bb.w;
        }
        #pragma unroll
        for (int r = 0; r < 4; r++)
            *(float4*)(s_sc + (size_t)(qi0 + r) * LKg + kt + ki0) =
                make_float4(acc[r][0], acc[r][1], acc[r][2], acc[r][3]);
    }
    __syncthreads();

    // ================= Phase 1.5: apply mask (mask stored as int32, 1 = masked out) ===
    const int* mg = M + ((size_t)b * LQg + q0) * LKg;
    for (int e = t * 4; e < TQ * LKg; e += NT * 4) {
        int4 m = *(const int4*)(mg + e);
        if (m.x) s_sc[e + 0] = NEG_BIG;
        if (m.y) s_sc[e + 1] = NEG_BIG;
        if (m.z) s_sc[e + 2] = NEG_BIG;
        if (m.w) s_sc[e + 3] = NEG_BIG;
    }
    __syncthreads();

    // ================= Phase 2: sparsemax (warp per row, Michelot) =================
    const int warp = t >> 5, lane = t & 31;
    for (int row = warp; row < TQ; row += NT / 32) {
        float* z = s_sc + (size_t)row * LKg;
        float zr[32];
        #pragma unroll
        for (int j = 0; j < 32; j++) zr[j] = z[lane + 32 * j];   // coalesced, conflict-free

        float S = 0.0f; int n = 0;
        #pragma unroll
        for (int j = 0; j < 32; j++)
            if (zr[j] > -1.0e29f) { S += zr[j]; n++; }
        #pragma unroll
        for (int o = 16; o; o >>= 1) {
            S += __shfl_xor_sync(0xffffffffu, S, o);
            n += __shfl_xor_sync(0xffffffffu, n, o);
        }

        float tau;
        if (n == 0) {
            tau = 3.0e38f;                 // fully-masked row -> all p = 0
        } else {
            tau = (S - 1.0f) / (float)n;
            for (int it = 0; it < 1024; it++) {
                float S2 = 0.0f; int n2 = 0;
                #pragma unroll
                for (int j = 0; j < 32; j++)
                    if (zr[j] > tau) { S2 += zr[j]; n2++; }
                #pragma unroll
                for (int o = 16; o; o >>= 1) {
                    S2 += __shfl_xor_sync(0xffffffffu, S2, o);
                    n2 += __shfl_xor_sync(0xffffffffu, n2, o);
                }
                if (n2 >= n) break;        // support stable -> converged (exact fixed point)
                n = n2;
                tau = (S2 - 1.0f) / (float)n2;
            }
        }

        float* arow = Attn + ((size_t)b * LQg + q0 + row) * LKg;
        #pragma unroll
        for (int j = 0; j < 32; j++) {
            float p = zr[j] - tau;
            p = p > 0.0f ? p : 0.0f;
            z[lane + 32 * j]    = p;       // for phase 3
            arow[lane + 32 * j] = p;       // coalesced attn output
        }
    }

    // ================= Phase 3: Out = P @ V =================
    const float* vg = V + (size_t)b * LKg * DH;
    const int do0 = (t & 31) << 1;   // 2 head dims per thread
    float oa[4][2] = {{0.f,0.f},{0.f,0.f},{0.f,0.f},{0.f,0.f}};

    for (int kt = 0; kt < LKg; kt += KT) {
        __syncthreads();   // also separates phase 2 smem writes from phase 3 reads
        for (int e = t; e < KT * DH; e += NT)
            s_kv[e] = vg[(size_t)kt * DH + e];          // natural [k][d] layout, fully coalesced
        __syncthreads();

        #pragma unroll 8
        for (int kk = 0; kk < KT; kk++) {
            float2 vv = *(const float2*)(s_kv + kk * DH + do0);   // conflict-free
            #pragma unroll
            for (int r = 0; r < 4; r++) {
                float p = s_sc[(size_t)(qi0 + r) * LKg + kt + kk]; // warp broadcast
                oa[r][0] += p * vv.x;
                oa[r][1] += p * vv.y;
            }
        }
    }

    float* og = Out + ((size_t)b * LQg + q0) * DH;
    #pragma unroll
    for (int r = 0; r < 4; r++)
        *(float2*)(og + (size_t)(qi0 + r) * DH + do0) = make_float2(oa[r][0], oa[r][1]);
}

extern "C" void kernel_launch(void* const* d_in, const int* in_sizes, int n_in,
                              void* d_out, int out_size)
{
    const float* q = (const float*)d_in[0];
    const float* k = (const float*)d_in[1];
    const float* v = (const float*)d_in[2];
    const int*   mask = (const int*)d_in[3];

    float* out  = (float*)d_out;                                  // [B, Lq, D]
    float* attn = out + (size_t)NB * LQg * DH;                    // [B, Lq, Lk]

    const size_t smem_bytes = (size_t)SMEM_FLOATS * sizeof(float);
    cudaFuncSetAttribute(sparse_attn_kernel,
                         cudaFuncAttributeMaxDynamicSharedMemorySize, (int)smem_bytes);

    dim3 grid(NB * (LQg / TQ));   // 2048 CTAs
    dim3 block(NT);
    sparse_attn_kernel<<<grid, block, smem_bytes>>>(q, k, v, mask, out, attn);
}

// round 7
// speedup vs baseline: 3.9034x; 3.9034x over previous
#include <cuda_runtime.h>
#include <cstdint>

#define NB   64
#define LQ   1024
#define LK   1024
#define DH   64
#define TQ   32          // query rows per CTA (4 per warp)
#define KT   128         // key tile
#define KTP  132         // padded smem stride
#define NT   256
#define NEG_BIG (-1.0e30f)

__global__ __launch_bounds__(NT, 4)
void sparse_attn_kernel(const float* __restrict__ Q, const float* __restrict__ K,
                        const float* __restrict__ V, const int* __restrict__ M,
                        float* __restrict__ Out, float* __restrict__ Attn)
{
    __shared__ float s_q[DH * TQ];    // [d][qi], 8 KB
    __shared__ float s_k[DH * KTP];   // [d][kj], 33.8 KB

    const int t    = threadIdx.x;
    const int b    = blockIdx.x >> 5;
    const int q0   = (blockIdx.x & 31) * TQ;
    const int warp = t >> 5, lane = t & 31;

    // ---- stage Q tile (scaled, transposed to [d][q]) ----
    const float* qg = Q + ((size_t)b * LQ + q0) * DH;
    for (int e = t; e < TQ * DH; e += NT) {
        int qi = e >> 6, d = e & 63;
        s_q[d * TQ + qi] = qg[e] * 0.125f;
    }

    const int qi0 = warp * 4;    // warp w owns rows 4w..4w+3 COMPLETELY
    const int ki0 = lane * 4;

    float* zbase = Attn + ((size_t)b * LQ + q0) * LK;   // scores staged in attn buffer

    // ================= Phase 1: S = (Q/T) @ K^T -> gmem (attn) =================
    const float* kg = K + (size_t)b * LK * DH;
    for (int kt = 0; kt < LK; kt += KT) {
        __syncthreads();
        for (int e = t; e < KT * DH; e += NT) {
            int kj = e >> 6, d = e & 63;
            s_k[d * KTP + kj] = kg[(size_t)(kt + kj) * DH + d];
        }
        __syncthreads();

        float acc[4][4];
        #pragma unroll
        for (int r = 0; r < 4; r++)
            #pragma unroll
            for (int c = 0; c < 4; c++) acc[r][c] = 0.0f;

        #pragma unroll 16
        for (int d = 0; d < DH; d++) {
            float4 a  = *(const float4*)(s_q + d * TQ  + qi0);   // warp broadcast
            float4 bb = *(const float4*)(s_k + d * KTP + ki0);   // conflict-free
            acc[0][0] += a.x * bb.x; acc[0][1] += a.x * bb.y; acc[0][2] += a.x * bb.z; acc[0][3] += a.x * bb.w;
            acc[1][0] += a.y * bb.x; acc[1][1] += a.y * bb.y; acc[1][2] += a.y * bb.z; acc[1][3] += a.y * bb.w;
            acc[2][0] += a.z * bb.x; acc[2][1] += a.z * bb.y; acc[2][2] += a.z * bb.z; acc[2][3] += a.z * bb.w;
            acc[3][0] += a.w * bb.x; acc[3][1] += a.w * bb.y; acc[3][2] += a.w * bb.z; acc[3][3] += a.w * bb.w;
        }
        #pragma unroll
        for (int r = 0; r < 4; r++)
            *(float4*)(zbase + (size_t)(qi0 + r) * LK + kt + ki0) =
                make_float4(acc[r][0], acc[r][1], acc[r][2], acc[r][3]);
    }

    __syncwarp();   // warp-local ordering: our rows were written entirely by this warp

    // ======= Phase 2+3 fused, per warp: mask + sparsemax + sparse P@V =======
    const float* vg = V + (size_t)b * LK * DH;
    const int*   mbase = M + ((size_t)b * LQ + q0) * LK;

    for (int r = 0; r < 4; r++) {
        const int row = qi0 + r;
        float*     z  = zbase + (size_t)row * LK;
        const int* mr = mbase + (size_t)row * LK;

        // load row + mask into registers: element k = 128*j + 4*lane + c
        float4 zr[8];
        float S = 0.0f; int n = 0;
        #pragma unroll
        for (int j = 0; j < 8; j++) {
            float4 zz = *(const float4*)(z  + j * 128 + lane * 4);
            int4   mm = *(const int4*)  (mr + j * 128 + lane * 4);
            zz.x = mm.x ? NEG_BIG : zz.x;
            zz.y = mm.y ? NEG_BIG : zz.y;
            zz.z = mm.z ? NEG_BIG : zz.z;
            zz.w = mm.w ? NEG_BIG : zz.w;
            zr[j] = zz;
            if (zz.x > -5.0e29f) { S += zz.x; n++; }
            if (zz.y > -5.0e29f) { S += zz.y; n++; }
            if (zz.z > -5.0e29f) { S += zz.z; n++; }
            if (zz.w > -5.0e29f) { S += zz.w; n++; }
        }
        #pragma unroll
        for (int o = 16; o; o >>= 1) {
            S += __shfl_xor_sync(0xffffffffu, S, o);
            n += __shfl_xor_sync(0xffffffffu, n, o);
        }

        float tau;
        if (n == 0) {
            tau = 3.0e38f;                       // fully-masked row -> p = 0 everywhere
        } else {
            tau = (S - 1.0f) / (float)n;
            for (int it = 0; it < 64; it++) {    // Michelot fixed point (exact)
                float S2 = 0.0f; int n2 = 0;
                #pragma unroll
                for (int j = 0; j < 8; j++) {
                    float4 zz = zr[j];
                    if (zz.x > tau) { S2 += zz.x; n2++; }
                    if (zz.y > tau) { S2 += zz.y; n2++; }
                    if (zz.z > tau) { S2 += zz.z; n2++; }
                    if (zz.w > tau) { S2 += zz.w; n2++; }
                }
                #pragma unroll
                for (int o = 16; o; o >>= 1) {
                    S2 += __shfl_xor_sync(0xffffffffu, S2, o);
                    n2 += __shfl_xor_sync(0xffffffffu, n2, o);
                }
                if (n2 >= n) break;
                n = n2;
                tau = (S2 - 1.0f) / (float)n2;
            }
        }

        // write p, accumulate sparse P@V (support is typically tiny)
        float2 oacc = make_float2(0.0f, 0.0f);
        #pragma unroll
        for (int j = 0; j < 8; j++) {
            float4 p;
            p.x = fmaxf(zr[j].x - tau, 0.0f);
            p.y = fmaxf(zr[j].y - tau, 0.0f);
            p.z = fmaxf(zr[j].z - tau, 0.0f);
            p.w = fmaxf(zr[j].w - tau, 0.0f);
            *(float4*)(z + j * 128 + lane * 4) = p;   // attn output (overwrites z)

            bool any = (p.x > 0.0f) | (p.y > 0.0f) | (p.z > 0.0f) | (p.w > 0.0f);
            unsigned bal = __ballot_sync(0xffffffffu, any);
            while (bal) {
                int L = __ffs(bal) - 1;
                bal &= bal - 1;
                float px = __shfl_sync(0xffffffffu, p.x, L);
                float py = __shfl_sync(0xffffffffu, p.y, L);
                float pz = __shfl_sync(0xffffffffu, p.z, L);
                float pw = __shfl_sync(0xffffffffu, p.w, L);
                const int kb = j * 128 + L * 4;
                if (px > 0.0f) {
                    float2 vv = *(const float2*)(vg + (size_t)(kb + 0) * DH + 2 * lane);
                    oacc.x += px * vv.x; oacc.y += px * vv.y;
                }
                if (py > 0.0f) {
                    float2 vv = *(const float2*)(vg + (size_t)(kb + 1) * DH + 2 * lane);
                    oacc.x += py * vv.x; oacc.y += py * vv.y;
                }
                if (pz > 0.0f) {
                    float2 vv = *(const float2*)(vg + (size_t)(kb + 2) * DH + 2 * lane);
                    oacc.x += pz * vv.x; oacc.y += pz * vv.y;
                }
                if (pw > 0.0f) {
                    float2 vv = *(const float2*)(vg + (size_t)(kb + 3) * DH + 2 * lane);
                    oacc.x += pw * vv.x; oacc.y += pw * vv.y;
                }
            }
        }

        *(float2*)(Out + ((size_t)b * LQ + q0 + row) * DH + 2 * lane) = oacc;
    }
}

extern "C" void kernel_launch(void* const* d_in, const int* in_sizes, int n_in,
                              void* d_out, int out_size)
{
    const float* q = (const float*)d_in[0];
    const float* k = (const float*)d_in[1];
    const float* v = (const float*)d_in[2];
    const int*   m = (const int*)d_in[3];

    float* out  = (float*)d_out;                 // [B, Lq, D]
    float* attn = out + (size_t)NB * LQ * DH;    // [B, Lq, Lk]

    dim3 grid(NB * (LQ / TQ));   // 2048 CTAs
    sparse_attn_kernel<<<grid, NT>>>(q, k, v, m, out, attn);
}

// round 12
// speedup vs baseline: 4.0278x; 1.0319x over previous
#include <cuda_runtime.h>
#include <cstdint>

#define NB   64
#define LQ   1024
#define LK   1024
#define DH   64
#define TQ   32          // query rows per CTA (4 per warp)
#define KT   128         // key tile
#define KTP  132         // padded smem stride
#define NT   256
#define NEG_BIG (-1.0e30f)

// ---- packed fp32x2 helpers (PTX ISA 8.6, sm_100 family -- NOT an 'a' feature) ----
__device__ __forceinline__ unsigned long long pack2(float x) {
    unsigned long long r;
    asm("mov.b64 %0, {%1, %1};" : "=l"(r) : "f"(x));
    return r;
}
__device__ __forceinline__ void ffma2(unsigned long long& d,
                                      unsigned long long a, unsigned long long b) {
    asm("fma.rn.f32x2 %0, %1, %2, %0;" : "+l"(d) : "l"(a), "l"(b));
}
__device__ __forceinline__ float2 unpack2(unsigned long long v) {
    float2 f;
    asm("mov.b64 {%0, %1}, %2;" : "=f"(f.x), "=f"(f.y) : "l"(v));
    return f;
}

__global__ __launch_bounds__(NT, 4)
void sparse_attn_kernel(const float* __restrict__ Q, const float* __restrict__ K,
                        const float* __restrict__ V, const int* __restrict__ M,
                        float* __restrict__ Out, float* __restrict__ Attn)
{
    __shared__ float s_q[DH * TQ];    // [d][qi], 8 KB
    __shared__ float s_k[DH * KTP];   // [d][kj], 33.8 KB

    const int t    = threadIdx.x;
    const int b    = blockIdx.x >> 5;
    const int q0   = (blockIdx.x & 31) * TQ;
    const int warp = t >> 5, lane = t & 31;

    // ---- stage Q tile (scaled, transposed to [d][q]) ----
    const float* qg = Q + ((size_t)b * LQ + q0) * DH;
    for (int e = t; e < TQ * DH; e += NT) {
        int qi = e >> 6, d = e & 63;
        s_q[d * TQ + qi] = qg[e] * 0.125f;
    }

    const int qi0 = warp * 4;    // warp w owns rows 4w..4w+3 COMPLETELY
    const int ki0 = lane * 4;

    float* zbase = Attn + ((size_t)b * LQ + q0) * LK;   // scores staged in attn buffer

    // ====== Phase 1: S = (Q/T) @ K^T -> gmem (attn), packed f32x2 FMA ======
    const float* kg = K + (size_t)b * LK * DH;
    for (int kt = 0; kt < LK; kt += KT) {
        __syncthreads();
        for (int e = t; e < KT * DH; e += NT) {
            int kj = e >> 6, d = e & 63;
            s_k[d * KTP + kj] = kg[(size_t)(kt + kj) * DH + d];
        }
        __syncthreads();

        unsigned long long acc2[4][2];
        #pragma unroll
        for (int r = 0; r < 4; r++) { acc2[r][0] = 0ull; acc2[r][1] = 0ull; }

        #pragma unroll 16
        for (int d = 0; d < DH; d++) {
            float4 a = *(const float4*)(s_q + d * TQ + qi0);              // warp broadcast
            ulonglong2 bb = *(const ulonglong2*)(s_k + d * KTP + ki0);    // 2 packed col-pairs
            unsigned long long pa;
            pa = pack2(a.x); ffma2(acc2[0][0], pa, bb.x); ffma2(acc2[0][1], pa, bb.y);
            pa = pack2(a.y); ffma2(acc2[1][0], pa, bb.x); ffma2(acc2[1][1], pa, bb.y);
            pa = pack2(a.z); ffma2(acc2[2][0], pa, bb.x); ffma2(acc2[2][1], pa, bb.y);
            pa = pack2(a.w); ffma2(acc2[3][0], pa, bb.x); ffma2(acc2[3][1], pa, bb.y);
        }
        #pragma unroll
        for (int r = 0; r < 4; r++) {
            float2 lo = unpack2(acc2[r][0]);
            float2 hi = unpack2(acc2[r][1]);
            *(float4*)(zbase + (size_t)(qi0 + r) * LK + kt + ki0) =
                make_float4(lo.x, lo.y, hi.x, hi.y);
        }
    }

    __syncwarp();   // warp-local ordering: our rows were written entirely by this warp

    // ======= Phase 2+3 fused, per warp: mask + sparsemax + sparse P@V =======
    const float* vg = V + (size_t)b * LK * DH;
    const int*   mbase = M + ((size_t)b * LQ + q0) * LK;

    for (int r = 0; r < 4; r++) {
        const int row = qi0 + r;
        float*     z  = zbase + (size_t)row * LK;
        const int* mr = mbase + (size_t)row * LK;

        // load row + mask into registers: element k = 128*j + 4*lane + c
        float4 zr[8];
        float S = 0.0f; int n = 0;
        #pragma unroll
        for (int j = 0; j < 8; j++) {
            float4 zz = *(const float4*)(z  + j * 128 + lane * 4);
            int4   mm = *(const int4*)  (mr + j * 128 + lane * 4);
            zz.x = mm.x ? NEG_BIG : zz.x;
            zz.y = mm.y ? NEG_BIG : zz.y;
            zz.z = mm.z ? NEG_BIG : zz.z;
            zz.w = mm.w ? NEG_BIG : zz.w;
            zr[j] = zz;
            if (zz.x > -5.0e29f) { S += zz.x; n++; }
            if (zz.y > -5.0e29f) { S += zz.y; n++; }
            if (zz.z > -5.0e29f) { S += zz.z; n++; }
            if (zz.w > -5.0e29f) { S += zz.w; n++; }
        }
        #pragma unroll
        for (int o = 16; o; o >>= 1) {
            S += __shfl_xor_sync(0xffffffffu, S, o);
            n += __shfl_xor_sync(0xffffffffu, n, o);
        }

        float tau;
        if (n == 0) {
            tau = 3.0e38f;                       // fully-masked row -> p = 0 everywhere
        } else {
            tau = (S - 1.0f) / (float)n;
            for (int it = 0; it < 64; it++) {    // Michelot fixed point (exact)
                float S2 = 0.0f; int n2 = 0;
                #pragma unroll
                for (int j = 0; j < 8; j++) {
                    float4 zz = zr[j];
                    if (zz.x > tau) { S2 += zz.x; n2++; }
                    if (zz.y > tau) { S2 += zz.y; n2++; }
                    if (zz.z > tau) { S2 += zz.z; n2++; }
                    if (zz.w > tau) { S2 += zz.w; n2++; }
                }
                #pragma unroll
                for (int o = 16; o; o >>= 1) {
                    S2 += __shfl_xor_sync(0xffffffffu, S2, o);
                    n2 += __shfl_xor_sync(0xffffffffu, n2, o);
                }
                if (n2 >= n) break;
                n = n2;
                tau = (S2 - 1.0f) / (float)n2;
            }
        }

        // write p, accumulate sparse P@V (support is typically tiny)
        float2 oacc = make_float2(0.0f, 0.0f);
        #pragma unroll
        for (int j = 0; j < 8; j++) {
            float4 p;
            p.x = fmaxf(zr[j].x - tau, 0.0f);
            p.y = fmaxf(zr[j].y - tau, 0.0f);
            p.z = fmaxf(zr[j].z - tau, 0.0f);
            p.w = fmaxf(zr[j].w - tau, 0.0f);
            *(float4*)(z + j * 128 + lane * 4) = p;   // attn output (overwrites z)

            bool any = (p.x > 0.0f) | (p.y > 0.0f) | (p.z > 0.0f) | (p.w > 0.0f);
            unsigned bal = __ballot_sync(0xffffffffu, any);
            while (bal) {
                int L = __ffs(bal) - 1;
                bal &= bal - 1;
                float px = __shfl_sync(0xffffffffu, p.x, L);
                float py = __shfl_sync(0xffffffffu, p.y, L);
                float pz = __shfl_sync(0xffffffffu, p.z, L);
                float pw = __shfl_sync(0xffffffffu, p.w, L);
                const int kb = j * 128 + L * 4;
                if (px > 0.0f) {
                    float2 vv = *(const float2*)(vg + (size_t)(kb + 0) * DH + 2 * lane);
                    oacc.x += px * vv.x; oacc.y += px * vv.y;
                }
                if (py > 0.0f) {
                    float2 vv = *(const float2*)(vg + (size_t)(kb + 1) * DH + 2 * lane);
                    oacc.x += py * vv.x; oacc.y += py * vv.y;
                }
                if (pz > 0.0f) {
                    float2 vv = *(const float2*)(vg + (size_t)(kb + 2) * DH + 2 * lane);
                    oacc.x += pz * vv.x; oacc.y += pz * vv.y;
                }
                if (pw > 0.0f) {
                    float2 vv = *(const float2*)(vg + (size_t)(kb + 3) * DH + 2 * lane);
                    oacc.x += pw * vv.x; oacc.y += pw * vv.y;
                }
            }
        }

        *(float2*)(Out + ((size_t)b * LQ + q0 + row) * DH + 2 * lane) = oacc;
    }
}

extern "C" void kernel_launch(void* const* d_in, const int* in_sizes, int n_in,
                              void* d_out, int out_size)
{
    const float* q = (const float*)d_in[0];
    const float* k = (const float*)d_in[1];
    const float* v = (const float*)d_in[2];
    const int*   m = (const int*)d_in[3];

    float* out  = (float*)d_out;                 // [B, Lq, D]
    float* attn = out + (size_t)NB * LQ * DH;    // [B, Lq, Lk]

    dim3 grid(NB * (LQ / TQ));   // 2048 CTAs
    sparse_attn_kernel<<<grid, NT>>>(q, k, v, m, out, attn);
}